// round 16
// baseline (speedup 1.0000x reference)
#include <cuda_runtime.h>
#include <cuda_fp16.h>
#include <mma.h>
#include <math.h>

using namespace nvcuda;

#define NN 50000
#define EE 400000
#define GG 64
#define FIN 16
#define HID 128
#define HEADS 4
#define C1 512   // HEADS*HID
#define MAXD 64  // padded adjacency stride; P(deg>=64)~1e-37 for Poisson(8)

// ---------------- scratch (static device memory; no allocs) ----------------
__device__ __half   g_h2h[NN * HID];      // fp16                12.8 MB
__device__ __half   g_w1h[FIN * C1];      // W1 fp16
__device__ __half   g_w2h[C1 * HID];      // W2 fp16
__device__ float    g_as1[NN * HEADS], g_ad1[NN * HEADS];
__device__ float    g_as2[NN], g_ad2[NN];
__device__ float    g_pool[GG * HID];
__device__ float    g_part1[GG * 128];    // bc1 + gf @ Wc1[128:160,:]
__device__ int      g_gstart[GG + 1];     // graph boundaries in sorted batch
// padded adjacency (by destination)
__device__ int      g_degc[NN];
__device__ int      g_nbr[NN * MAXD];

// ---------------- helpers ----------------
__device__ __forceinline__ float leaky(float x) { return x > 0.f ? x : 0.2f * x; }
__device__ __forceinline__ float eluf(float x)  { return x > 0.f ? x : expm1f(x); }

__device__ __forceinline__ float4 h4_to_f4(uint2 u) {
    __half2 a = *(__half2*)&u.x, b = *(__half2*)&u.y;
    float2 fa = __half22float2(a), fb = __half22float2(b);
    return make_float4(fa.x, fa.y, fb.x, fb.y);
}
__device__ __forceinline__ uint2 f4_to_h4(float4 v) {
    __half2 a = __floats2half2_rn(v.x, v.y), b = __floats2half2_rn(v.z, v.w);
    uint2 u; u.x = *(unsigned*)&a; u.y = *(unsigned*)&b; return u;
}
__device__ __forceinline__ void red_add_f32(float* p, float v) {
    asm volatile("red.global.add.f32 [%0], %1;" :: "l"(p), "f"(v) : "memory");
}

// ---------------- K1 (mega): weight convert + logits + adjacency + boundaries
//                  + graph MLP + partial classifier (pool-independent work) ----
__global__ void k_mega(const float* __restrict__ x, const float* __restrict__ W1,
                       const float* __restrict__ W2,
                       const float* __restrict__ as1, const float* __restrict__ ad1,
                       const int* __restrict__ src, const int* __restrict__ dst,
                       const int* __restrict__ batch,
                       const float* __restrict__ gfeat,
                       const float* __restrict__ Wg1, const float* __restrict__ bg1,
                       const float* __restrict__ Wg2, const float* __restrict__ bg2,
                       const float* __restrict__ Wc1, const float* __restrict__ bc1) {
    __shared__ float ws[FIN * HEADS], wd[FIN * HEADS];
    __shared__ float hg1[GG * 32];
    __shared__ float gf2[GG * 32];
    int t = threadIdx.x;
    int b = blockIdx.x;
    int gidx = b * 256 + t;

    // weight conversion
    if (gidx < C1 * HID) g_w2h[gidx] = __float2half_rn(W2[gidx]);
    if (gidx < FIN * C1) g_w1h[gidx] = __float2half_rn(W1[gidx]);

    // graph boundaries: last block, threads 0..64 (parallel searches)
    if (b == gridDim.x - 1 && t <= GG) {
        int lo = 0, hi = NN;
        while (lo < hi) { int m = (lo + hi) >> 1; if (batch[m] < t) lo = m + 1; else hi = m; }
        g_gstart[t] = lo;
    }

    // graph-feature MLP + partial classifier: block grid-2
    if (b == gridDim.x - 2) {
        for (int idx = t; idx < GG * 32; idx += 256) {
            int g = idx >> 5, c = idx & 31;
            float s = bg1[c];
#pragma unroll
            for (int k = 0; k < 10; k++) s += gfeat[g * 10 + k] * Wg1[k * 32 + c];
            hg1[idx] = fmaxf(s, 0.f);
        }
        __syncthreads();
        for (int idx = t; idx < GG * 32; idx += 256) {
            int g = idx >> 5, c = idx & 31;
            float s = bg2[c];
#pragma unroll
            for (int k = 0; k < 32; k++) s += hg1[g * 32 + k] * Wg2[k * 32 + c];
            gf2[idx] = s;
        }
        __syncthreads();
        for (int idx = t; idx < GG * 128; idx += 256) {
            int g = idx >> 7, c = idx & 127;
            float s = bc1[c];
#pragma unroll
            for (int j = 0; j < 32; j++) s += gf2[g * 32 + j] * Wc1[(128 + j) * 128 + c];
            g_part1[idx] = s;
        }
    }

    // fold attention vectors + per-node logits (blocks 0..195)
    if (b < 196) {
        if (t < 128) {
            int idx = t & 63;
            int k = idx >> 2, h = idx & 3;
            const float* av = (t < 64) ? as1 : ad1;
            float s = 0.f;
            for (int c = 0; c < HID; c++) s += W1[k * C1 + h * HID + c] * av[h * HID + c];
            if (t < 64) ws[idx] = s; else wd[idx] = s;
        }
        __syncthreads();
        int n = gidx;
        if (n < NN) {
            float xr[FIN];
            const float4* xp = (const float4*)(x + n * FIN);
#pragma unroll
            for (int i = 0; i < 4; i++) {
                float4 v = xp[i];
                xr[i * 4 + 0] = v.x; xr[i * 4 + 1] = v.y;
                xr[i * 4 + 2] = v.z; xr[i * 4 + 3] = v.w;
            }
#pragma unroll
            for (int h = 0; h < HEADS; h++) {
                float s = 0.f, d = 0.f;
#pragma unroll
                for (int k = 0; k < FIN; k++) {
                    s += xr[k] * ws[k * 4 + h];
                    d += xr[k] * wd[k * 4 + h];
                }
                g_as1[n * 4 + h] = s;
                g_ad1[n * 4 + h] = d;
            }
        }
    }

    // adjacency fill (degc pre-zeroed by memset node)
    if (gidx < EE) {
        int d = dst[gidx];
        int slot = atomicAdd(&g_degc[d], 1);
        if (slot < MAXD) g_nbr[d * MAXD + slot] = src[gidx];
    }
}

// ---------------- K2: fused z-aggregation + layer1-transform + layer2 GEMM -----
#define F_LD 136
#define Z_LD 72
#define W1_LD 520
#define OFF_AS 0
#define OFF_BS 34816
#define OFF_ZS 69632
#define OFF_W1 88064
#define OFF_B1 104704
#define OFF_SA 106752
#define OFF_SD 107264
#define SMEM_TOT 107776

__global__ __launch_bounds__(512) void k_fused2(
    const float* __restrict__ x, const float* __restrict__ b1,
    const float* __restrict__ as2, const float* __restrict__ ad2) {
    extern __shared__ __align__(16) char smem[];
    __half* As  = (__half*)(smem + OFF_AS);
    float*  Cs  = (float*)(smem + OFF_AS);     // alias (epilogue only)
    __half* Bs  = (__half*)(smem + OFF_BS);
    __half* zs  = (__half*)(smem + OFF_ZS);
    __half* w1s = (__half*)(smem + OFF_W1);
    float*  sb1 = (float*)(smem + OFF_B1);
    float*  sa  = (float*)(smem + OFF_SA);
    float*  sd  = (float*)(smem + OFF_SD);

    int t = threadIdx.x;
    int wid = t >> 5, lane = t & 31;
    int wm = wid >> 1, wn = wid & 1;
    int row0 = blockIdx.x * 128;

    if (t < C1) sb1[t] = b1[t];
    if (t < HID) { sa[t] = as2[t]; sd[t] = ad2[t]; }
#pragma unroll
    for (int j = 0; j < 16; j++) {
        int idx = t + j * 512;
        int r = idx >> 9, c = idx & 511;
        w1s[r * W1_LD + c] = g_w1h[idx];
    }

    // ---- z-stage: node = row0 + (t>>2), head = t&3 ----
    {
        int nid = t >> 2, h = t & 3;
        int n = row0 + nid;
        __half* zp = &zs[nid * Z_LD + h * 16];
        if (n < NN) {
            int deg = min(g_degc[n], MAXD);
            const int* nb = &g_nbr[n * MAXD];
            float adn = g_ad1[n * 4 + h];
            float a = __expf(leaky(g_as1[n * 4 + h] + adn));   // self-loop
            float S = a;
            float z[16];
            const float4* xp = (const float4*)(x + n * FIN);
#pragma unroll
            for (int q = 0; q < 4; q++) {
                float4 v = xp[q];
                z[q * 4 + 0] = a * v.x; z[q * 4 + 1] = a * v.y;
                z[q * 4 + 2] = a * v.z; z[q * 4 + 3] = a * v.w;
            }
            for (int p = 0; p < deg; p++) {
                int s = nb[p];
                float av = __expf(leaky(g_as1[s * 4 + h] + adn));
                S += av;
                const float4* sp = (const float4*)(x + s * FIN);
#pragma unroll
                for (int q = 0; q < 4; q++) {
                    float4 v = sp[q];
                    z[q * 4 + 0] += av * v.x; z[q * 4 + 1] += av * v.y;
                    z[q * 4 + 2] += av * v.z; z[q * 4 + 3] += av * v.w;
                }
            }
            float Sinv = 1.f / S;
#pragma unroll
            for (int q = 0; q < 4; q++) {
                float4 v = make_float4(z[q * 4 + 0] * Sinv, z[q * 4 + 1] * Sinv,
                                       z[q * 4 + 2] * Sinv, z[q * 4 + 3] * Sinv);
                *(uint2*)&zp[q * 4] = f4_to_h4(v);
            }
        } else {
            uint2 zz; zz.x = 0u; zz.y = 0u;
#pragma unroll
            for (int q = 0; q < 4; q++) *(uint2*)&zp[q * 4] = zz;
        }
    }

    wmma::fragment<wmma::accumulator, 16, 16, 16, float> acc[4];
#pragma unroll
    for (int i = 0; i < 4; i++) wmma::fill_fragment(acc[i], 0.f);
    __syncthreads();

    for (int h = 0; h < 4; h++) {
        int kt = h * 128;
        {
            wmma::fragment<wmma::matrix_a, 16, 16, 16, __half, wmma::row_major> af;
            wmma::load_matrix_sync(af, &zs[wm * 16 * Z_LD + h * 16], Z_LD);
#pragma unroll
            for (int nf = 0; nf < 4; nf++) {
                wmma::fragment<wmma::accumulator, 16, 16, 16, __half> acc2;
                wmma::fill_fragment(acc2, __float2half(0.f));
                wmma::fragment<wmma::matrix_b, 16, 16, 16, __half, wmma::row_major> bf;
                wmma::load_matrix_sync(bf, &w1s[kt + wn * 64 + nf * 16], W1_LD);
                wmma::mma_sync(acc2, af, bf, acc2);
                wmma::store_matrix_sync(&As[wm * 16 * F_LD + wn * 64 + nf * 16], acc2,
                                        F_LD, wmma::mem_row_major);
            }
        }
#pragma unroll
        for (int j = 0; j < 8; j++) {
            int idx = t + j * 512;
            int r = idx >> 5, c4 = idx & 31;
            *(uint2*)&Bs[r * F_LD + c4 * 4] = ((const uint2*)g_w2h)[(kt + r) * 32 + c4];
        }
        __syncthreads();
#pragma unroll
        for (int j = 0; j < 32; j++) {
            int idx = t + j * 512;
            int r = idx >> 7, c = idx & 127;
            float v = __half2float(As[r * F_LD + c]) + sb1[kt + c];
            As[r * F_LD + c] = __float2half_rn(eluf(v));
        }
        __syncthreads();
#pragma unroll
        for (int kk = 0; kk < 8; kk++) {
            wmma::fragment<wmma::matrix_a, 16, 16, 16, __half, wmma::row_major> af;
            wmma::load_matrix_sync(af, &As[wm * 16 * F_LD + kk * 16], F_LD);
#pragma unroll
            for (int nf = 0; nf < 4; nf++) {
                wmma::fragment<wmma::matrix_b, 16, 16, 16, __half, wmma::row_major> bf;
                wmma::load_matrix_sync(bf, &Bs[kk * 16 * F_LD + wn * 64 + nf * 16], F_LD);
                wmma::mma_sync(acc[nf], af, bf, acc[nf]);
            }
        }
        __syncthreads();
    }
#pragma unroll
    for (int nf = 0; nf < 4; nf++)
        wmma::store_matrix_sync(&Cs[wm * 16 * F_LD + wn * 64 + nf * 16], acc[nf],
                                F_LD, wmma::mem_row_major);
    __syncthreads();
    {
        int r2 = t >> 2, seg = t & 3;
        int row = row0 + r2;
        if (row < NN) {
            uint2* dstp = (uint2*)&g_h2h[row * HID];
#pragma unroll
            for (int j = 0; j < 8; j++) {
                int c4 = seg * 8 + j;
                float4 v = make_float4(Cs[r2 * F_LD + c4 * 4 + 0], Cs[r2 * F_LD + c4 * 4 + 1],
                                       Cs[r2 * F_LD + c4 * 4 + 2], Cs[r2 * F_LD + c4 * 4 + 3]);
                dstp[c4] = f4_to_h4(v);
            }
        }
    }
#pragma unroll
    for (int i = 0; i < 8; i++) {
        int rI = wid * 8 + i;
        int row = row0 + rI;
        float s = 0.f, d = 0.f;
#pragma unroll
        for (int c = 0; c < 4; c++) {
            float v = Cs[rI * F_LD + lane + c * 32];
            s += v * sa[lane + c * 32];
            d += v * sd[lane + c * 32];
        }
#pragma unroll
        for (int o = 16; o > 0; o >>= 1) {
            s += __shfl_xor_sync(0xffffffffu, s, o);
            d += __shfl_xor_sync(0xffffffffu, d, o);
        }
        if (lane == 0 && row < NN) { g_as2[row] = s; g_ad2[row] = d; }
    }
}

// ---------------- K3: layer2 gather + fused mean-pool (1 exp/edge) -------------
__global__ void k_agg2pool(const int* __restrict__ batch, const float* __restrict__ b2) {
    __shared__ int   ssrc[8][MAXD];
    __shared__ float sev[8][MAXD];
    __shared__ float sy[8][128];
    __shared__ int   sg[8];
    int t = threadIdx.x;
    int w = t >> 5, lane = t & 31;
    int n = blockIdx.x * 8 + w;
    if (n < NN) {
        int deg = min(g_degc[n], MAXD);
        const int* nb = &g_nbr[n * MAXD];
        float adn = g_ad2[n];
        float Sp = 0.f;
        for (int i = lane; i < deg; i += 32) {
            int s = nb[i];
            float ev = __expf(leaky(g_as2[s] + adn));
            ssrc[w][i] = s; sev[w][i] = ev;
            Sp += ev;
        }
#pragma unroll
        for (int o = 16; o > 0; o >>= 1) Sp += __shfl_xor_sync(0xffffffffu, Sp, o);
        float evself = __expf(leaky(g_as2[n] + adn));
        float Sinv = 1.f / (Sp + evself);
        __syncwarp();
        const uint2* h2p = (const uint2*)g_h2h;
        float4 v = h4_to_f4(h2p[n * 32 + lane]);
        float4 acc = make_float4(evself * v.x, evself * v.y, evself * v.z, evself * v.w);
        int e = 0;
        for (; e + 1 < deg; e += 2) {
            int s0 = ssrc[w][e], s1 = ssrc[w][e + 1];
            float a0 = sev[w][e], a1 = sev[w][e + 1];
            float4 v0 = h4_to_f4(h2p[s0 * 32 + lane]);
            float4 v1 = h4_to_f4(h2p[s1 * 32 + lane]);
            acc.x += a0 * v0.x + a1 * v1.x;
            acc.y += a0 * v0.y + a1 * v1.y;
            acc.z += a0 * v0.z + a1 * v1.z;
            acc.w += a0 * v0.w + a1 * v1.w;
        }
        if (e < deg) {
            int s0 = ssrc[w][e];
            float a0 = sev[w][e];
            float4 v0 = h4_to_f4(h2p[s0 * 32 + lane]);
            acc.x += a0 * v0.x; acc.y += a0 * v0.y;
            acc.z += a0 * v0.z; acc.w += a0 * v0.w;
        }
        float4 bb = *(const float4*)&b2[lane * 4];
        float4 y = make_float4(eluf(acc.x * Sinv + bb.x), eluf(acc.y * Sinv + bb.y),
                               eluf(acc.z * Sinv + bb.z), eluf(acc.w * Sinv + bb.w));
        *(float4*)&sy[w][lane * 4] = y;
        if (lane == 0) sg[w] = batch[n];
    } else if (lane == 0) sg[w] = -1;
    __syncthreads();
    if (t < 128) {
        float acc = 0.f;
        int curg = -1;
#pragma unroll
        for (int r = 0; r < 8; r++) {
            int g = sg[r];
            if (g != curg) {
                if (curg >= 0) red_add_f32(&g_pool[curg * HID + t], acc);
                curg = g; acc = 0.f;
            }
            if (g >= 0) acc += sy[r][t];
        }
        if (curg >= 0) red_add_f32(&g_pool[curg * HID + t], acc);
    }
}

// ---------------- K4: classifier (pool-dependent half; parallel both stages) ---
__global__ void k_final(const float* __restrict__ Wc1, const float* __restrict__ Wc2,
                        const float* __restrict__ bc2, float* __restrict__ out) {
    int g = blockIdx.x;
    int t = threadIdx.x;   // 192 threads (6 warps)
    __shared__ float z[128];
    __shared__ float t1[128];
    __shared__ float w2s[128 * 6];
    // preload Wc2 into smem (parallel with z load)
    for (int i = t; i < 128 * 6; i += 192) w2s[i] = Wc2[i];
    if (t < 128) {
        float cnt = (float)(g_gstart[g + 1] - g_gstart[g]);
        float inv = 1.f / fmaxf(cnt, 1.f);
        z[t] = g_pool[g * HID + t] * inv;
    }
    __syncthreads();
    if (t < 128) {
        float s = g_part1[g * 128 + t];
#pragma unroll 8
        for (int k = 0; k < 128; k++) s += z[k] * Wc1[k * 128 + t];
        t1[t] = fmaxf(s, 0.f);
    }
    __syncthreads();
    {
        int c = t >> 5, lane = t & 31;   // warp c handles class c
        float s = 0.f;
#pragma unroll
        for (int k = lane; k < 128; k += 32) s += t1[k] * w2s[k * 6 + c];
#pragma unroll
        for (int o = 16; o > 0; o >>= 1) s += __shfl_xor_sync(0xffffffffu, s, o);
        if (lane == 0) out[g * 6 + c] = s + bc2[c];
    }
}

// ---------------- launch ----------------
extern "C" void kernel_launch(void* const* d_in, const int* in_sizes, int n_in,
                              void* d_out, int out_size) {
    const float* x     = (const float*)d_in[0];
    const int*   ei    = (const int*)d_in[1];
    const int*   batch = (const int*)d_in[2];
    const float* gfeat = (const float*)d_in[3];
    const float* W1    = (const float*)d_in[4];
    const float* as1   = (const float*)d_in[5];
    const float* ad1   = (const float*)d_in[6];
    const float* b1    = (const float*)d_in[7];
    const float* W2    = (const float*)d_in[8];
    const float* as2   = (const float*)d_in[9];
    const float* ad2   = (const float*)d_in[10];
    const float* b2    = (const float*)d_in[11];
    const float* Wg1   = (const float*)d_in[12];
    const float* bg1   = (const float*)d_in[13];
    const float* Wg2   = (const float*)d_in[14];
    const float* bg2   = (const float*)d_in[15];
    const float* Wc1   = (const float*)d_in[16];
    const float* bc1   = (const float*)d_in[17];
    const float* Wc2   = (const float*)d_in[18];
    const float* bc2   = (const float*)d_in[19];
    float* out = (float*)d_out;

    const int* src = ei;
    const int* dst = ei + EE;

    cudaFuncSetAttribute(k_fused2, cudaFuncAttributeMaxDynamicSharedMemorySize, SMEM_TOT);

    void* p_degc = nullptr; void* p_pool = nullptr;
    cudaGetSymbolAddress(&p_degc, g_degc);
    cudaGetSymbolAddress(&p_pool, g_pool);
    cudaMemsetAsync(p_degc, 0, NN * sizeof(int));
    cudaMemsetAsync(p_pool, 0, GG * HID * sizeof(float));

    k_mega<<<(EE + 255) / 256, 256>>>(x, W1, W2, as1, ad1, src, dst, batch,
                                      gfeat, Wg1, bg1, Wg2, bg2, Wc1, bc1);
    k_fused2<<<(NN + 127) / 128, 512, SMEM_TOT>>>(x, b1, as2, ad2);
    k_agg2pool<<<(NN + 7) / 8, 256>>>(batch, b2);
    k_final<<<GG, 192>>>(Wc1, Wc2, bc2, out);
}

// round 17
// speedup vs baseline: 1.0479x; 1.0479x over previous
#include <cuda_runtime.h>
#include <cuda_fp16.h>
#include <mma.h>
#include <math.h>

using namespace nvcuda;

#define NN 50000
#define EE 400000
#define GG 64
#define FIN 16
#define HID 128
#define HEADS 4
#define C1 512   // HEADS*HID
#define MAXD 64  // padded adjacency stride; P(deg>=64)~1e-37 for Poisson(8)

// ---------------- scratch (static device memory; no allocs) ----------------
__device__ __half   g_h2h[NN * HID];      // fp16                12.8 MB
__device__ __half   g_w1h[FIN * C1];      // W1 fp16
__device__ __half   g_w2h[C1 * HID];      // W2 fp16
__device__ float    g_as1[NN * HEADS], g_ad1[NN * HEADS];
__device__ float    g_as2[NN], g_ad2[NN];
__device__ float    g_pool[GG * HID];
__device__ float    g_part1[GG * 128];    // bc1 + gf @ Wc1[128:160,:]
__device__ int      g_gstart[GG + 1];     // graph boundaries in sorted batch
__device__ float    g_sink;               // L2 pre-touch sink (never actually written)
// padded adjacency (by destination)
__device__ int      g_degc[NN];
__device__ int      g_nbr[NN * MAXD];

// ---------------- helpers ----------------
__device__ __forceinline__ float leaky(float x) { return x > 0.f ? x : 0.2f * x; }
__device__ __forceinline__ float eluf(float x)  { return x > 0.f ? x : expm1f(x); }

__device__ __forceinline__ float4 h4_to_f4(uint2 u) {
    __half2 a = *(__half2*)&u.x, b = *(__half2*)&u.y;
    float2 fa = __half22float2(a), fb = __half22float2(b);
    return make_float4(fa.x, fa.y, fb.x, fb.y);
}
__device__ __forceinline__ uint2 f4_to_h4(float4 v) {
    __half2 a = __floats2half2_rn(v.x, v.y), b = __floats2half2_rn(v.z, v.w);
    uint2 u; u.x = *(unsigned*)&a; u.y = *(unsigned*)&b; return u;
}
__device__ __forceinline__ void red_add_f32(float* p, float v) {
    asm volatile("red.global.add.f32 [%0], %1;" :: "l"(p), "f"(v) : "memory");
}

// ---------------- K1 (mega): weight convert + logits + adjacency + boundaries
//                  + graph MLP + partial classifier + Wc1 L2 pre-touch ---------
__global__ void k_mega(const float* __restrict__ x, const float* __restrict__ W1,
                       const float* __restrict__ W2,
                       const float* __restrict__ as1, const float* __restrict__ ad1,
                       const int* __restrict__ src, const int* __restrict__ dst,
                       const int* __restrict__ batch,
                       const float* __restrict__ gfeat,
                       const float* __restrict__ Wg1, const float* __restrict__ bg1,
                       const float* __restrict__ Wg2, const float* __restrict__ bg2,
                       const float* __restrict__ Wc1, const float* __restrict__ bc1) {
    __shared__ float ws[FIN * HEADS], wd[FIN * HEADS];
    __shared__ float hg1[GG * 32];
    __shared__ float gf2[GG * 32];
    int t = threadIdx.x;
    int b = blockIdx.x;
    int gidx = b * 256 + t;

    // weight conversion
    if (gidx < C1 * HID) g_w2h[gidx] = __float2half_rn(W2[gidx]);
    if (gidx < FIN * C1) g_w1h[gidx] = __float2half_rn(W1[gidx]);

    // L2 pre-touch of Wc1 (keeps it resident for k_final's first wave)
    if (gidx < 128 * 128) {
        float v = __ldg(&Wc1[gidx]);
        if (__float_as_uint(v) == 0xDEADBEEFu) g_sink = v;   // never taken in practice
    }

    // graph boundaries: last block, threads 0..64 (parallel searches)
    if (b == gridDim.x - 1 && t <= GG) {
        int lo = 0, hi = NN;
        while (lo < hi) { int m = (lo + hi) >> 1; if (batch[m] < t) lo = m + 1; else hi = m; }
        g_gstart[t] = lo;
    }

    // graph-feature MLP + partial classifier: block grid-2
    if (b == gridDim.x - 2) {
        for (int idx = t; idx < GG * 32; idx += 256) {
            int g = idx >> 5, c = idx & 31;
            float s = bg1[c];
#pragma unroll
            for (int k = 0; k < 10; k++) s += gfeat[g * 10 + k] * Wg1[k * 32 + c];
            hg1[idx] = fmaxf(s, 0.f);
        }
        __syncthreads();
        for (int idx = t; idx < GG * 32; idx += 256) {
            int g = idx >> 5, c = idx & 31;
            float s = bg2[c];
#pragma unroll
            for (int k = 0; k < 32; k++) s += hg1[g * 32 + k] * Wg2[k * 32 + c];
            gf2[idx] = s;
        }
        __syncthreads();
        for (int idx = t; idx < GG * 128; idx += 256) {
            int g = idx >> 7, c = idx & 127;
            float s = bc1[c];
#pragma unroll
            for (int j = 0; j < 32; j++) s += gf2[g * 32 + j] * Wc1[(128 + j) * 128 + c];
            g_part1[idx] = s;
        }
    }

    // fold attention vectors + per-node logits (blocks 0..195)
    if (b < 196) {
        if (t < 128) {
            int idx = t & 63;
            int k = idx >> 2, h = idx & 3;
            const float* av = (t < 64) ? as1 : ad1;
            float s = 0.f;
            for (int c = 0; c < HID; c++) s += W1[k * C1 + h * HID + c] * av[h * HID + c];
            if (t < 64) ws[idx] = s; else wd[idx] = s;
        }
        __syncthreads();
        int n = gidx;
        if (n < NN) {
            float xr[FIN];
            const float4* xp = (const float4*)(x + n * FIN);
#pragma unroll
            for (int i = 0; i < 4; i++) {
                float4 v = xp[i];
                xr[i * 4 + 0] = v.x; xr[i * 4 + 1] = v.y;
                xr[i * 4 + 2] = v.z; xr[i * 4 + 3] = v.w;
            }
#pragma unroll
            for (int h = 0; h < HEADS; h++) {
                float s = 0.f, d = 0.f;
#pragma unroll
                for (int k = 0; k < FIN; k++) {
                    s += xr[k] * ws[k * 4 + h];
                    d += xr[k] * wd[k * 4 + h];
                }
                g_as1[n * 4 + h] = s;
                g_ad1[n * 4 + h] = d;
            }
        }
    }

    // adjacency fill (degc pre-zeroed by memset node)
    if (gidx < EE) {
        int d = dst[gidx];
        int slot = atomicAdd(&g_degc[d], 1);
        if (slot < MAXD) g_nbr[d * MAXD + slot] = src[gidx];
    }
}

// ---------------- K2: fused z-aggregation + layer1-transform + layer2 GEMM -----
#define F_LD 136
#define Z_LD 72
#define W1_LD 520
#define OFF_AS 0
#define OFF_BS 34816
#define OFF_ZS 69632
#define OFF_W1 88064
#define OFF_B1 104704
#define OFF_SA 106752
#define OFF_SD 107264
#define SMEM_TOT 107776

__global__ __launch_bounds__(512) void k_fused2(
    const float* __restrict__ x, const float* __restrict__ b1,
    const float* __restrict__ as2, const float* __restrict__ ad2) {
    extern __shared__ __align__(16) char smem[];
    __half* As  = (__half*)(smem + OFF_AS);
    float*  Cs  = (float*)(smem + OFF_AS);     // alias (epilogue only)
    __half* Bs  = (__half*)(smem + OFF_BS);
    __half* zs  = (__half*)(smem + OFF_ZS);
    __half* w1s = (__half*)(smem + OFF_W1);
    float*  sb1 = (float*)(smem + OFF_B1);
    float*  sa  = (float*)(smem + OFF_SA);
    float*  sd  = (float*)(smem + OFF_SD);

    int t = threadIdx.x;
    int wid = t >> 5, lane = t & 31;
    int wm = wid >> 1, wn = wid & 1;
    int row0 = blockIdx.x * 128;

    if (t < C1) sb1[t] = b1[t];
    if (t < HID) { sa[t] = as2[t]; sd[t] = ad2[t]; }
#pragma unroll
    for (int j = 0; j < 16; j++) {
        int idx = t + j * 512;
        int r = idx >> 9, c = idx & 511;
        w1s[r * W1_LD + c] = g_w1h[idx];
    }

    // ---- z-stage: node = row0 + (t>>2), head = t&3 ----
    {
        int nid = t >> 2, h = t & 3;
        int n = row0 + nid;
        __half* zp = &zs[nid * Z_LD + h * 16];
        if (n < NN) {
            int deg = min(g_degc[n], MAXD);
            const int* nb = &g_nbr[n * MAXD];
            float adn = g_ad1[n * 4 + h];
            float a = __expf(leaky(g_as1[n * 4 + h] + adn));   // self-loop
            float S = a;
            float z[16];
            const float4* xp = (const float4*)(x + n * FIN);
#pragma unroll
            for (int q = 0; q < 4; q++) {
                float4 v = xp[q];
                z[q * 4 + 0] = a * v.x; z[q * 4 + 1] = a * v.y;
                z[q * 4 + 2] = a * v.z; z[q * 4 + 3] = a * v.w;
            }
            for (int p = 0; p < deg; p++) {
                int s = nb[p];
                float av = __expf(leaky(g_as1[s * 4 + h] + adn));
                S += av;
                const float4* sp = (const float4*)(x + s * FIN);
#pragma unroll
                for (int q = 0; q < 4; q++) {
                    float4 v = sp[q];
                    z[q * 4 + 0] += av * v.x; z[q * 4 + 1] += av * v.y;
                    z[q * 4 + 2] += av * v.z; z[q * 4 + 3] += av * v.w;
                }
            }
            float Sinv = 1.f / S;
#pragma unroll
            for (int q = 0; q < 4; q++) {
                float4 v = make_float4(z[q * 4 + 0] * Sinv, z[q * 4 + 1] * Sinv,
                                       z[q * 4 + 2] * Sinv, z[q * 4 + 3] * Sinv);
                *(uint2*)&zp[q * 4] = f4_to_h4(v);
            }
        } else {
            uint2 zz; zz.x = 0u; zz.y = 0u;
#pragma unroll
            for (int q = 0; q < 4; q++) *(uint2*)&zp[q * 4] = zz;
        }
    }

    wmma::fragment<wmma::accumulator, 16, 16, 16, float> acc[4];
#pragma unroll
    for (int i = 0; i < 4; i++) wmma::fill_fragment(acc[i], 0.f);
    __syncthreads();

    for (int h = 0; h < 4; h++) {
        int kt = h * 128;
        {
            wmma::fragment<wmma::matrix_a, 16, 16, 16, __half, wmma::row_major> af;
            wmma::load_matrix_sync(af, &zs[wm * 16 * Z_LD + h * 16], Z_LD);
#pragma unroll
            for (int nf = 0; nf < 4; nf++) {
                wmma::fragment<wmma::accumulator, 16, 16, 16, __half> acc2;
                wmma::fill_fragment(acc2, __float2half(0.f));
                wmma::fragment<wmma::matrix_b, 16, 16, 16, __half, wmma::row_major> bf;
                wmma::load_matrix_sync(bf, &w1s[kt + wn * 64 + nf * 16], W1_LD);
                wmma::mma_sync(acc2, af, bf, acc2);
                wmma::store_matrix_sync(&As[wm * 16 * F_LD + wn * 64 + nf * 16], acc2,
                                        F_LD, wmma::mem_row_major);
            }
        }
#pragma unroll
        for (int j = 0; j < 8; j++) {
            int idx = t + j * 512;
            int r = idx >> 5, c4 = idx & 31;
            *(uint2*)&Bs[r * F_LD + c4 * 4] = ((const uint2*)g_w2h)[(kt + r) * 32 + c4];
        }
        __syncthreads();
#pragma unroll
        for (int j = 0; j < 32; j++) {
            int idx = t + j * 512;
            int r = idx >> 7, c = idx & 127;
            float v = __half2float(As[r * F_LD + c]) + sb1[kt + c];
            As[r * F_LD + c] = __float2half_rn(eluf(v));
        }
        __syncthreads();
#pragma unroll
        for (int kk = 0; kk < 8; kk++) {
            wmma::fragment<wmma::matrix_a, 16, 16, 16, __half, wmma::row_major> af;
            wmma::load_matrix_sync(af, &As[wm * 16 * F_LD + kk * 16], F_LD);
#pragma unroll
            for (int nf = 0; nf < 4; nf++) {
                wmma::fragment<wmma::matrix_b, 16, 16, 16, __half, wmma::row_major> bf;
                wmma::load_matrix_sync(bf, &Bs[kk * 16 * F_LD + wn * 64 + nf * 16], F_LD);
                wmma::mma_sync(acc[nf], af, bf, acc[nf]);
            }
        }
        __syncthreads();
    }
#pragma unroll
    for (int nf = 0; nf < 4; nf++)
        wmma::store_matrix_sync(&Cs[wm * 16 * F_LD + wn * 64 + nf * 16], acc[nf],
                                F_LD, wmma::mem_row_major);
    __syncthreads();
    {
        int r2 = t >> 2, seg = t & 3;
        int row = row0 + r2;
        if (row < NN) {
            uint2* dstp = (uint2*)&g_h2h[row * HID];
#pragma unroll
            for (int j = 0; j < 8; j++) {
                int c4 = seg * 8 + j;
                float4 v = make_float4(Cs[r2 * F_LD + c4 * 4 + 0], Cs[r2 * F_LD + c4 * 4 + 1],
                                       Cs[r2 * F_LD + c4 * 4 + 2], Cs[r2 * F_LD + c4 * 4 + 3]);
                dstp[c4] = f4_to_h4(v);
            }
        }
    }
#pragma unroll
    for (int i = 0; i < 8; i++) {
        int rI = wid * 8 + i;
        int row = row0 + rI;
        float s = 0.f, d = 0.f;
#pragma unroll
        for (int c = 0; c < 4; c++) {
            float v = Cs[rI * F_LD + lane + c * 32];
            s += v * sa[lane + c * 32];
            d += v * sd[lane + c * 32];
        }
#pragma unroll
        for (int o = 16; o > 0; o >>= 1) {
            s += __shfl_xor_sync(0xffffffffu, s, o);
            d += __shfl_xor_sync(0xffffffffu, d, o);
        }
        if (lane == 0 && row < NN) { g_as2[row] = s; g_ad2[row] = d; }
    }
}

// ---------------- K3: layer2 gather + fused mean-pool (1 exp/edge) -------------
__global__ void k_agg2pool(const int* __restrict__ batch, const float* __restrict__ b2) {
    __shared__ int   ssrc[8][MAXD];
    __shared__ float sev[8][MAXD];
    __shared__ float sy[8][128];
    __shared__ int   sg[8];
    int t = threadIdx.x;
    int w = t >> 5, lane = t & 31;
    int n = blockIdx.x * 8 + w;
    if (n < NN) {
        int deg = min(g_degc[n], MAXD);
        const int* nb = &g_nbr[n * MAXD];
        float adn = g_ad2[n];
        float Sp = 0.f;
        for (int i = lane; i < deg; i += 32) {
            int s = nb[i];
            float ev = __expf(leaky(g_as2[s] + adn));
            ssrc[w][i] = s; sev[w][i] = ev;
            Sp += ev;
        }
#pragma unroll
        for (int o = 16; o > 0; o >>= 1) Sp += __shfl_xor_sync(0xffffffffu, Sp, o);
        float evself = __expf(leaky(g_as2[n] + adn));
        float Sinv = 1.f / (Sp + evself);
        __syncwarp();
        const uint2* h2p = (const uint2*)g_h2h;
        float4 v = h4_to_f4(h2p[n * 32 + lane]);
        float4 acc = make_float4(evself * v.x, evself * v.y, evself * v.z, evself * v.w);
        int e = 0;
        for (; e + 1 < deg; e += 2) {
            int s0 = ssrc[w][e], s1 = ssrc[w][e + 1];
            float a0 = sev[w][e], a1 = sev[w][e + 1];
            float4 v0 = h4_to_f4(h2p[s0 * 32 + lane]);
            float4 v1 = h4_to_f4(h2p[s1 * 32 + lane]);
            acc.x += a0 * v0.x + a1 * v1.x;
            acc.y += a0 * v0.y + a1 * v1.y;
            acc.z += a0 * v0.z + a1 * v1.z;
            acc.w += a0 * v0.w + a1 * v1.w;
        }
        if (e < deg) {
            int s0 = ssrc[w][e];
            float a0 = sev[w][e];
            float4 v0 = h4_to_f4(h2p[s0 * 32 + lane]);
            acc.x += a0 * v0.x; acc.y += a0 * v0.y;
            acc.z += a0 * v0.z; acc.w += a0 * v0.w;
        }
        float4 bb = *(const float4*)&b2[lane * 4];
        float4 y = make_float4(eluf(acc.x * Sinv + bb.x), eluf(acc.y * Sinv + bb.y),
                               eluf(acc.z * Sinv + bb.z), eluf(acc.w * Sinv + bb.w));
        *(float4*)&sy[w][lane * 4] = y;
        if (lane == 0) sg[w] = batch[n];
    } else if (lane == 0) sg[w] = -1;
    __syncthreads();
    if (t < 128) {
        float acc = 0.f;
        int curg = -1;
#pragma unroll
        for (int r = 0; r < 8; r++) {
            int g = sg[r];
            if (g != curg) {
                if (curg >= 0) red_add_f32(&g_pool[curg * HID + t], acc);
                curg = g; acc = 0.f;
            }
            if (g >= 0) acc += sy[r][t];
        }
        if (curg >= 0) red_add_f32(&g_pool[curg * HID + t], acc);
    }
}

// ---------------- K4: classifier (parallel-k matvec, 512 threads) --------------
__global__ void k_final(const float* __restrict__ Wc1, const float* __restrict__ Wc2,
                        const float* __restrict__ bc2, float* __restrict__ out) {
    int g = blockIdx.x;
    int t = threadIdx.x;   // 512 threads
    __shared__ float z[128];
    __shared__ float part[4][128];
    __shared__ float t1[128];
    __shared__ float w2s[128 * 6];
    for (int i = t; i < 128 * 6; i += 512) w2s[i] = Wc2[i];
    if (t < 128) {
        float cnt = (float)(g_gstart[g + 1] - g_gstart[g]);
        float inv = 1.f / fmaxf(cnt, 1.f);
        z[t] = g_pool[g * HID + t] * inv;
    }
    __syncthreads();
    {
        int c = t & 127, j = t >> 7;    // 4 k-groups of 32
        float s = 0.f;
        int k0 = j * 32;
#pragma unroll
        for (int k = 0; k < 32; k++) s += z[k0 + k] * Wc1[(k0 + k) * 128 + c];
        part[j][c] = s;
    }
    __syncthreads();
    if (t < 128) {
        float s = g_part1[g * 128 + t] + ((part[0][t] + part[1][t]) + (part[2][t] + part[3][t]));
        t1[t] = fmaxf(s, 0.f);
    }
    __syncthreads();
    if (t < 192) {
        int c = t >> 5, lane = t & 31;   // warp c handles class c
        float s = 0.f;
#pragma unroll
        for (int k = lane; k < 128; k += 32) s += t1[k] * w2s[k * 6 + c];
#pragma unroll
        for (int o = 16; o > 0; o >>= 1) s += __shfl_xor_sync(0xffffffffu, s, o);
        if (lane == 0) out[g * 6 + c] = s + bc2[c];
    }
}

// ---------------- launch ----------------
extern "C" void kernel_launch(void* const* d_in, const int* in_sizes, int n_in,
                              void* d_out, int out_size) {
    const float* x     = (const float*)d_in[0];
    const int*   ei    = (const int*)d_in[1];
    const int*   batch = (const int*)d_in[2];
    const float* gfeat = (const float*)d_in[3];
    const float* W1    = (const float*)d_in[4];
    const float* as1   = (const float*)d_in[5];
    const float* ad1   = (const float*)d_in[6];
    const float* b1    = (const float*)d_in[7];
    const float* W2    = (const float*)d_in[8];
    const float* as2   = (const float*)d_in[9];
    const float* ad2   = (const float*)d_in[10];
    const float* b2    = (const float*)d_in[11];
    const float* Wg1   = (const float*)d_in[12];
    const float* bg1   = (const float*)d_in[13];
    const float* Wg2   = (const float*)d_in[14];
    const float* bg2   = (const float*)d_in[15];
    const float* Wc1   = (const float*)d_in[16];
    const float* bc1   = (const float*)d_in[17];
    const float* Wc2   = (const float*)d_in[18];
    const float* bc2   = (const float*)d_in[19];
    float* out = (float*)d_out;

    const int* src = ei;
    const int* dst = ei + EE;

    cudaFuncSetAttribute(k_fused2, cudaFuncAttributeMaxDynamicSharedMemorySize, SMEM_TOT);

    void* p_degc = nullptr; void* p_pool = nullptr;
    cudaGetSymbolAddress(&p_degc, g_degc);
    cudaGetSymbolAddress(&p_pool, g_pool);
    cudaMemsetAsync(p_degc, 0, NN * sizeof(int));
    cudaMemsetAsync(p_pool, 0, GG * HID * sizeof(float));

    k_mega<<<(EE + 255) / 256, 256>>>(x, W1, W2, as1, ad1, src, dst, batch,
                                      gfeat, Wg1, bg1, Wg2, bg2, Wc1, bc1);
    k_fused2<<<(NN + 127) / 128, 512, SMEM_TOT>>>(x, b1, as2, ad2);
    k_agg2pool<<<(NN + 7) / 8, 256>>>(batch, b2);
    k_final<<<GG, 512>>>(Wc1, Wc2, bc2, out);
}